// round 14
// baseline (speedup 1.0000x reference)
#include <cuda_runtime.h>
#include <cuda_fp16.h>
#include <math.h>

#define B_    32
#define N_    512
#define H_    8
#define ACT_  4
#define ALPHA_ 0.2f

typedef unsigned long long ull;

// ---- packed f32x2 helpers (sm_100+) ----
__device__ __forceinline__ ull ffma2(ull a, ull b, ull c) {
    ull d; asm("fma.rn.f32x2 %0, %1, %2, %3;" : "=l"(d) : "l"(a), "l"(b), "l"(c)); return d;
}
__device__ __forceinline__ ull add2(ull a, ull b) {
    ull d; asm("add.rn.f32x2 %0, %1, %2;" : "=l"(d) : "l"(a), "l"(b)); return d;
}
__device__ __forceinline__ ull pack2(float lo, float hi) {
    ull r; asm("mov.b64 %0, {%1,%2};" : "=l"(r) : "f"(lo), "f"(hi)); return r;
}
__device__ __forceinline__ void unpack2(ull v, float& lo, float& hi) {
    asm("mov.b64 {%0,%1}, %2;" : "=f"(lo), "=f"(hi) : "l"(v));
}

// ---------------- device scratch ----------------
__device__ float g_Wh  [B_*H_*N_*64];
__device__ float g_ssrc[B_*H_*N_];
__device__ float g_sdst[B_*H_*N_];
__device__ float g_x   [B_*N_*H_*64];
__device__ float g_Wh2 [B_*N_*64];
__device__ float g_s2s [B_*N_];
__device__ float g_s2d [B_*N_];
__device__ float g_h2  [B_*N_*64];
__device__ float g_z1p [32*B_*256];

// =====================================================================
// GEMM v3: 128 rows x 64 cols per block, 256 threads = 2 K-half groups.
// A transposed in smem ([k][row], pad 132) -> LDS.128 yields packed
// row-pairs for ffma2. B natural [k][col]. acc = 4 row-pairs x 8 cols.
// Register split-K combined through smem; epilogue + s-dots by group 0.
// =====================================================================
#define GEMM_SMEM (2*(32*132 + 32*64)*4)   // 50176 B

__global__ __launch_bounds__(256)
void gemm_s_kernel(const float* __restrict__ A,
                   const float* __restrict__ Ball,
                   const float* __restrict__ aSrc,
                   const float* __restrict__ aDst,
                   float* __restrict__ Cout,
                   float* __restrict__ sSrc,
                   float* __restrict__ sDst,
                   int K, int outBatch, int outHead, int sBatch)
{
    extern __shared__ float smf[];
    int tid = threadIdx.x;          // 256
    int grp = tid >> 7;             // 0,1 : K-half
    int t   = tid & 127;
    float* As_t = smf + grp*(32*132 + 32*64);
    float* Bs   = As_t + 32*132;

    int r0 = blockIdx.x * 128;
    int h  = blockIdx.y;
    int b  = r0 / N_;
    int n0 = r0 % N_;
    const float* Bmat = Ball + (size_t)h*K*64;

    int tr = t >> 3;     // 0..15 -> rows tr*8..+7
    int tc = t & 7;      // 0..7  -> cols tc*8..+7

    ull acc[4][8];
#pragma unroll
    for (int rp = 0; rp < 4; rp++)
#pragma unroll
        for (int c = 0; c < 8; c++) acc[rp][c] = 0ull;

    int halfK  = K >> 1;
    int kstart = grp * halfK;
    int nIter  = halfK >> 5;        // K/64

    for (int it = 0; it < nIter; it++) {
        int kb = kstart + it*32;
        // A: 128 rows x 32 k, coalesced float4 reads, transposed STS
#pragma unroll
        for (int l = 0; l < 8; l++) {
            int lin = l*128 + t;              // 1024 float4
            int row = lin >> 3;
            int kq4 = lin & 7;
            float4 v = *(const float4*)&A[(size_t)(r0+row)*K + kb + kq4*4];
            As_t[(kq4*4+0)*132 + row] = v.x;
            As_t[(kq4*4+1)*132 + row] = v.y;
            As_t[(kq4*4+2)*132 + row] = v.z;
            As_t[(kq4*4+3)*132 + row] = v.w;
        }
        // B: 32 k x 64 cols, direct
#pragma unroll
        for (int l = 0; l < 4; l++) {
            int lin = l*128 + t;              // 512 float4
            int kk = lin >> 4;
            int cq = lin & 15;
            *(float4*)&Bs[kk*64 + cq*4] = *(const float4*)&Bmat[(size_t)(kb+kk)*64 + cq*4];
        }
        __syncthreads();
#pragma unroll 4
        for (int k = 0; k < 32; k++) {
            ulonglong2 a01 = *(const ulonglong2*)&As_t[k*132 + tr*8];
            ulonglong2 a23 = *(const ulonglong2*)&As_t[k*132 + tr*8 + 4];
            float4 bl = *(const float4*)&Bs[k*64 + tc*8];
            float4 bh = *(const float4*)&Bs[k*64 + tc*8 + 4];
            ull ar[4] = {a01.x, a01.y, a23.x, a23.y};
            ull bb[8];
            bb[0] = pack2(bl.x, bl.x); bb[1] = pack2(bl.y, bl.y);
            bb[2] = pack2(bl.z, bl.z); bb[3] = pack2(bl.w, bl.w);
            bb[4] = pack2(bh.x, bh.x); bb[5] = pack2(bh.y, bh.y);
            bb[6] = pack2(bh.z, bh.z); bb[7] = pack2(bh.w, bh.w);
#pragma unroll
            for (int rp = 0; rp < 4; rp++)
#pragma unroll
                for (int c = 0; c < 8; c++)
                    acc[rp][c] = ffma2(ar[rp], bb[c], acc[rp][c]);
        }
        __syncthreads();
    }

    // combine the two K-half groups through smem
    ull* xch = (ull*)smf;            // 128*32 ull = 32 KB
    if (grp == 1) {
#pragma unroll
        for (int rp = 0; rp < 4; rp++)
#pragma unroll
            for (int c = 0; c < 8; c++)
                xch[t*32 + rp*8 + c] = acc[rp][c];
    }
    __syncthreads();
    if (grp == 0) {
#pragma unroll
        for (int rp = 0; rp < 4; rp++)
#pragma unroll
            for (int c = 0; c < 8; c++)
                acc[rp][c] = add2(acc[rp][c], xch[t*32 + rp*8 + c]);

        const float* aS = aSrc + (size_t)h*64;
        const float* aD = aDst + (size_t)h*64;
        float aSv[8], aDv[8];
#pragma unroll
        for (int j = 0; j < 8; j++) {
            aSv[j] = __ldg(&aS[tc*8 + j]);
            aDv[j] = __ldg(&aD[tc*8 + j]);
        }
        float* outP = Cout + (size_t)b*outBatch + (size_t)h*outHead + (size_t)n0*64;

#pragma unroll
        for (int rp = 0; rp < 4; rp++) {
            float lo[8], hi[8];
#pragma unroll
            for (int c = 0; c < 8; c++) unpack2(acc[rp][c], lo[c], hi[c]);
#pragma unroll
            for (int e = 0; e < 2; e++) {
                float* v = e ? hi : lo;
                int row = tr*8 + rp*2 + e;
                *(float4*)&outP[(size_t)row*64 + tc*8    ] = make_float4(v[0], v[1], v[2], v[3]);
                *(float4*)&outP[(size_t)row*64 + tc*8 + 4] = make_float4(v[4], v[5], v[6], v[7]);
                float ss = 0.f, sd = 0.f;
#pragma unroll
                for (int c = 0; c < 8; c++) {
                    ss = fmaf(v[c], aSv[c], ss);
                    sd = fmaf(v[c], aDv[c], sd);
                }
#pragma unroll
                for (int off = 4; off > 0; off >>= 1) {
                    ss += __shfl_down_sync(0xffffffffu, ss, off, 8);
                    sd += __shfl_down_sync(0xffffffffu, sd, off, 8);
                }
                if (tc == 0) {
                    int n = n0 + row;
                    sSrc[(size_t)b*sBatch + (size_t)h*N_ + n] = ss;
                    sDst[(size_t)b*sBatch + (size_t)h*N_ + n] = sd;
                }
            }
        }
    }
}

// =====================================================================
// Sorted-prefix GAT attend (R11 v5): qSplit blocks per group.
// =====================================================================
struct AttSmem {
    __half2 Whp[512*32];               // 64 KB
    ull p2[512], q2[512];              // 8 KB
    ull cP2[33*32], cQ2[33*32];        // 16.5 KB
    float sdp[512], ss[512], Pp[512], Pq[512];
    int   perm[512], kq[512];
    float wtP[16], wtQ[16];
};

__global__ void attend_kernel(const float* __restrict__ Wh,
                              const float* __restrict__ sS,
                              const float* __restrict__ sD,
                              float* __restrict__ out,
                              int outBatch, int outHead, int rowStride,
                              int hPerB, int applyElu, int qSplit)
{
    extern __shared__ char smraw[];
    AttSmem& s = *reinterpret_cast<AttSmem*>(smraw);
    int tid  = threadIdx.x;            // 512
    int lane = tid & 31, wid = tid >> 5;
    int g  = blockIdx.x / qSplit;
    int qo = blockIdx.x % qSplit;
    int b = g / hPerB, h = g % hPerB;
    const float* WhG = Wh + (size_t)g*512*64;

    float key = sD[(size_t)g*512 + tid];
    int   val = tid;
    s.ss[tid] = sS[(size_t)g*512 + tid];

    for (int k = 2; k <= 512; k <<= 1) {
        int j = k >> 1;
        for (; j >= 32; j >>= 1) {
            s.sdp[tid] = key; s.perm[tid] = val;
            __syncthreads();
            float ok = s.sdp[tid ^ j];
            int   ov = s.perm[tid ^ j];
            __syncthreads();
            bool keepMin = ((tid & k) == 0) == ((tid & j) == 0);
            bool take = keepMin ? (ok < key) : (ok > key);
            if (take) { key = ok; val = ov; }
        }
        for (; j >= 1; j >>= 1) {
            float ok = __shfl_xor_sync(0xffffffffu, key, j);
            int   ov = __shfl_xor_sync(0xffffffffu, val, j);
            bool keepMin = ((tid & k) == 0) == ((tid & j) == 0);
            bool take = keepMin ? (ok < key) : (ok > key);
            if (take) { key = ok; val = ov; }
        }
    }
    s.sdp[tid] = key; s.perm[tid] = val;
    __syncthreads();

    float dmax = s.sdp[511];
    float pv = __expf(key - dmax);
    float qv = __expf(ALPHA_ * (key - dmax));
    s.p2[tid] = pack2(pv, pv);
    s.q2[tid] = pack2(qv, qv);

    float ip = pv, iq = qv;
#pragma unroll
    for (int off = 1; off < 32; off <<= 1) {
        float np = __shfl_up_sync(0xffffffffu, ip, off);
        float nq = __shfl_up_sync(0xffffffffu, iq, off);
        if (lane >= off) { ip += np; iq += nq; }
    }
    if (lane == 31) { s.wtP[wid] = ip; s.wtQ[wid] = iq; }
    __syncthreads();
    float offP = 0.f, offQ = 0.f;
    for (int w2 = 0; w2 < wid; w2++) { offP += s.wtP[w2]; offQ += s.wtQ[w2]; }
    s.Pp[tid] = ip + offP;
    s.Pq[tid] = iq + offQ;

    {
        float ky = -s.ss[tid];
        int lo = 0, hi = 512;
        while (lo < hi) { int mid = (lo+hi) >> 1; if (s.sdp[mid] <= ky) lo = mid+1; else hi = mid; }
        s.kq[tid] = lo;
    }

    for (int j = wid; j < 512; j += 16) {
        float2 v = *(const float2*)&WhG[(size_t)s.perm[j]*64 + 2*lane];
        s.Whp[j*32 + lane] = __floats2half2_rn(v.x, v.y);
    }
    __syncthreads();

#pragma unroll
    for (int cc = 0; cc < 2; cc++) {
        int c = wid*2 + cc;
        ull aP = 0ull, aQ = 0ull;
#pragma unroll
        for (int t2 = 0; t2 < 16; t2++) {
            int row = c*16 + t2;
            float2 wf = __half22float2(s.Whp[row*32 + lane]);
            ull w2 = pack2(wf.x, wf.y);
            aP = ffma2(w2, s.p2[row], aP);
            aQ = ffma2(w2, s.q2[row], aQ);
        }
        s.cP2[c*32 + lane] = aP;
        s.cQ2[c*32 + lane] = aQ;
    }
    __syncthreads();

    int e0 = tid, e1 = tid + 512;
    int c0e = e0 >> 5, c1e = e1 >> 5;
#pragma unroll
    for (int d = 1; d < 32; d <<= 1) {
        ull v0P = s.cP2[e0], v1P = s.cP2[e1];
        ull v0Q = s.cQ2[e0], v1Q = s.cQ2[e1];
        ull a0P = (c0e >= d) ? s.cP2[e0 - 32*d] : 0ull;
        ull a1P = (c1e >= d) ? s.cP2[e1 - 32*d] : 0ull;
        ull a0Q = (c0e >= d) ? s.cQ2[e0 - 32*d] : 0ull;
        ull a1Q = (c1e >= d) ? s.cQ2[e1 - 32*d] : 0ull;
        __syncthreads();
        s.cP2[e0] = add2(v0P, a0P); s.cP2[e1] = add2(v1P, a1P);
        s.cQ2[e0] = add2(v0Q, a0Q); s.cQ2[e1] = add2(v1Q, a1Q);
        __syncthreads();
    }
    {
        ull i0P = s.cP2[e0], i1P = s.cP2[e1];
        ull i0Q = s.cQ2[e0], i1Q = s.cQ2[e1];
        __syncthreads();
        s.cP2[e0 + 32] = i0P; s.cP2[e1 + 32] = i1P;
        s.cQ2[e0 + 32] = i0Q; s.cQ2[e1 + 32] = i1Q;
        if (tid < 32) { s.cP2[tid] = 0ull; s.cQ2[tid] = 0ull; }
        __syncthreads();
    }

    float totS = s.Pp[511];
    float totPx, totPy; unpack2(s.cP2[32*32 + lane], totPx, totPy);
    float* outRow = out + (size_t)b*outBatch + (size_t)h*outHead;

    int qLen = 512 / qSplit;
    int itCount = qLen >> 4;
    int qBase = qo * qLen;
    for (int it = 0; it < itCount; it++) {
        int i = qBase + it*16 + wid;
        int kk = s.kq[i];
        float sv = s.ss[i];
        int c = kk >> 4, r = kk & 15;
        bool fwd = (r <= 8);
        int cb = fwd ? c : (c + 1);
        ull exP = s.cP2[cb*32 + lane], exQ = s.cQ2[cb*32 + lane];
        int t0 = fwd ? (c << 4) : kk;
        int t1 = fwd ? kk : ((c + 1) << 4);
        ull aP = 0ull, aQ = 0ull;
        for (int t2 = t0; t2 < t1; t2++) {
            float2 wf = __half22float2(s.Whp[t2*32 + lane]);
            ull w2 = pack2(wf.x, wf.y);
            aP = ffma2(w2, s.p2[t2], aP);
            aQ = ffma2(w2, s.q2[t2], aQ);
        }
        float sign = fwd ? 1.f : -1.f;
        float exPx, exPy, exQx, exQy, aPx, aPy, aQx, aQy;
        unpack2(exP, exPx, exPy); unpack2(exQ, exQx, exQy);
        unpack2(aP, aPx, aPy);   unpack2(aQ, aQx, aQy);
        float vPx = fmaf(sign, aPx, exPx), vPy = fmaf(sign, aPy, exPy);
        float vQx = fmaf(sign, aQx, exQx), vQy = fmaf(sign, aQy, exQy);

        float spx = kk ? s.Pp[kk-1] : 0.f;
        float sqx = kk ? s.Pq[kk-1] : 0.f;
        float spd = sv + dmax;
        float m   = spd > 0.f ? spd : ALPHA_*spd;
        float Af  = __expf(spd - m);
        float Bf  = __expf(ALPHA_*spd - m);
        float invZ = 1.f / (Af*(totS - spx) + Bf*sqx);
        float vx = (Af*(totPx - vPx) + Bf*vQx) * invZ;
        float vy = (Af*(totPy - vPy) + Bf*vQy) * invZ;
        if (applyElu) {
            vx = vx > 0.f ? vx : (__expf(vx) - 1.f);
            vy = vy > 0.f ? vy : (__expf(vy) - 1.f);
        }
        *(float2*)&outRow[(size_t)i*rowStride + 2*lane] = make_float2(vx, vy);
    }
}

// =====================================================================
// fc1 split-K, W staged through smem
// =====================================================================
__global__ void fc1_kernel(const float* __restrict__ W)
{
    __shared__ float z_s[32*40];
    __shared__ float w_s[32*64];
    int tid = threadIdx.x;       // 256
    int cb = blockIdx.x;         // 0..3
    int ks = blockIdx.y;         // 0..31
    int rg = tid >> 5;
    int cl = tid & 31;
    int c0 = cl*2;
    int kbase = ks*1024;

    ull a0[4], a1[4];
#pragma unroll
    for (int i = 0; i < 4; i++) { a0[i] = 0ull; a1[i] = 0ull; }

    for (int kk = 0; kk < 1024; kk += 32) {
#pragma unroll
        for (int t = 0; t < 4; t++) {
            int lin = t*256 + tid;
            int row = lin >> 5, k2 = lin & 31;
            z_s[row*40 + k2] = g_h2[(size_t)row*32768 + kbase + kk + k2];
        }
#pragma unroll
        for (int t = 0; t < 8; t++) {
            int lin = t*256 + tid;
            int k2 = lin >> 6, o = lin & 63;
            w_s[k2*64 + o] = W[(size_t)(kbase + kk + k2)*256 + cb*64 + o];
        }
        __syncthreads();
#pragma unroll 2
        for (int kq = 0; kq < 8; kq++) {
            float2 w0 = *(const float2*)&w_s[(4*kq+0)*64 + c0];
            float2 w1 = *(const float2*)&w_s[(4*kq+1)*64 + c0];
            float2 w2 = *(const float2*)&w_s[(4*kq+2)*64 + c0];
            float2 w3 = *(const float2*)&w_s[(4*kq+3)*64 + c0];
            ull wa0 = pack2(w0.x, w1.x), wa1 = pack2(w2.x, w3.x);
            ull wb0 = pack2(w0.y, w1.y), wb1 = pack2(w2.y, w3.y);
#pragma unroll
            for (int i = 0; i < 4; i++) {
                ulonglong2 zz = *(const ulonglong2*)&z_s[(rg*4+i)*40 + 4*kq];
                a0[i] = ffma2(zz.x, wa0, a0[i]);
                a1[i] = ffma2(zz.x, wb0, a1[i]);
                a0[i] = ffma2(zz.y, wa1, a0[i]);
                a1[i] = ffma2(zz.y, wb1, a1[i]);
            }
        }
        __syncthreads();
    }
#pragma unroll
    for (int i = 0; i < 4; i++) {
        float s0lo, s0hi, s1lo, s1hi;
        unpack2(a0[i], s0lo, s0hi); unpack2(a1[i], s1lo, s1hi);
        g_z1p[(size_t)ks*8192 + (rg*4+i)*256 + cb*64 + c0    ] = s0lo + s0hi;
        g_z1p[(size_t)ks*8192 + (rg*4+i)*256 + cb*64 + c0 + 1] = s1lo + s1hi;
    }
}

// =====================================================================
// head: reduce fc1 partials + relu -> fc2 relu -> fc3 tanh
// =====================================================================
__global__ void head_kernel(const float* __restrict__ fc1_b,
                            const float* __restrict__ fc2_w,
                            const float* __restrict__ fc2_b,
                            const float* __restrict__ fc3_w,
                            const float* __restrict__ fc3_b,
                            float* __restrict__ out)
{
    __shared__ float z2[256], z3[256], red[256];
    int b = blockIdx.x, t = threadIdx.x;
    float v = fc1_b[t];
#pragma unroll
    for (int ks = 0; ks < 32; ks++) v += g_z1p[(size_t)ks*8192 + b*256 + t];
    z2[t] = v > 0.f ? v : 0.f;
    __syncthreads();
    float y = fc2_b[t];
#pragma unroll 8
    for (int k = 0; k < 256; k++) y += z2[k] * fc2_w[(size_t)k*256 + t];
    z3[t] = y > 0.f ? y : 0.f;
    __syncthreads();
    {
        int act = t & 3, grp = t >> 2;
        float partial = 0.f;
#pragma unroll
        for (int u = 0; u < 4; u++) {
            int k = grp*4 + u;
            partial += z3[k] * fc3_w[k*ACT_ + act];
        }
        red[t] = partial;
    }
    __syncthreads();
    if (t < ACT_) {
        float a = fc3_b[t];
#pragma unroll
        for (int j = 0; j < 64; j++) a += red[j*4 + t];
        out[b*ACT_ + t] = tanhf(a);
    }
}

// =====================================================================
extern "C" void kernel_launch(void* const* d_in, const int* in_sizes, int n_in,
                              void* d_out, int out_size)
{
    (void)in_sizes; (void)n_in; (void)out_size;
    const float* state     = (const float*)d_in[0];
    const float* W_heads   = (const float*)d_in[1];
    const float* a_src     = (const float*)d_in[2];
    const float* a_dst     = (const float*)d_in[3];
    const float* W_out     = (const float*)d_in[4];
    const float* a_out_src = (const float*)d_in[5];
    const float* a_out_dst = (const float*)d_in[6];
    const float* fc1_w     = (const float*)d_in[7];
    const float* fc1_b     = (const float*)d_in[8];
    const float* fc2_w     = (const float*)d_in[9];
    const float* fc2_b     = (const float*)d_in[10];
    const float* fc3_w     = (const float*)d_in[11];
    const float* fc3_b     = (const float*)d_in[12];
    float* out = (float*)d_out;

    float *pWh, *pss, *psd, *px, *pWh2, *ps2s, *ps2d, *ph2;
    cudaGetSymbolAddress((void**)&pWh,  g_Wh);
    cudaGetSymbolAddress((void**)&pss,  g_ssrc);
    cudaGetSymbolAddress((void**)&psd,  g_sdst);
    cudaGetSymbolAddress((void**)&px,   g_x);
    cudaGetSymbolAddress((void**)&pWh2, g_Wh2);
    cudaGetSymbolAddress((void**)&ps2s, g_s2s);
    cudaGetSymbolAddress((void**)&ps2d, g_s2d);
    cudaGetSymbolAddress((void**)&ph2,  g_h2);

    int attSmem = (int)sizeof(AttSmem);
    cudaFuncSetAttribute(attend_kernel, cudaFuncAttributeMaxDynamicSharedMemorySize, attSmem);
    cudaFuncSetAttribute(gemm_s_kernel, cudaFuncAttributeMaxDynamicSharedMemorySize, GEMM_SMEM);

    // Layer 1 GEMM: 1024 blocks, 128 rows each
    gemm_s_kernel<<<dim3(128, 8), 256, GEMM_SMEM>>>(state, W_heads, a_src, a_dst,
                                                    pWh, pss, psd,
                                                    64, H_*N_*64, N_*64, H_*N_);
    // Attend 1 + ELU
    attend_kernel<<<256, 512, attSmem>>>(pWh, pss, psd, px,
                                         N_*H_*64, 64, H_*64, H_, 1, 1);
    // Layer 2 GEMM: 128 blocks, K=512 (register split-K inside block)
    gemm_s_kernel<<<dim3(128, 1), 256, GEMM_SMEM>>>(px, W_out, a_out_src, a_out_dst,
                                                    pWh2, ps2s, ps2d,
                                                    512, N_*64, 0, N_);
    // Attend 2, query-split 4-way
    attend_kernel<<<128, 512, attSmem>>>(pWh2, ps2s, ps2d, ph2,
                                         N_*64, 0, 64, 1, 0, 4);
    fc1_kernel<<<dim3(4, 32), 256>>>(fc1_w);
    head_kernel<<<32, 256>>>(fc1_b, fc2_w, fc2_b, fc3_w, fc3_b, out);
}